// round 6
// baseline (speedup 1.0000x reference)
#include <cuda_runtime.h>
#include <cstdint>
#include <cstddef>

// ---------------- problem constants ----------------
#define C_INC   128
#define C_OUTC  256
#define HDIM    64
#define WDIM    64
#define BSZ     16
#define KKC     1152          // C_IN * 9
#define KWORDS  288           // KKC / 4
#define M_TOT   65536
#define L_IMG   4096

// ---------------- k_aq staging ----------------
#define SSTR  1156
#define AQ_SMEM (KKC*4 + 8*3*66*4 + 64*SSTR)

// ---------------- GEMM tiling ----------------
#define BM   128
#define BN   128
#define KT_STEPS 18           // 18 chunks of 64 B
#define ASTRIDE 80            // smem bytes per row (64 data + 16 pad)
#define ASTAGE  (BM * ASTRIDE)

// ---------------- device scratch ----------------
__device__ float g_wscale[KKC];
__device__ float g_ascale[KKC];
__device__ float g_scale[KKC];
__device__ float g_qfx[KKC];
__device__ float g_sx;
__device__ float g_sw;
__device__ __align__(16) int8_t g_wq[C_OUTC * KKC];
__device__ __align__(16) int8_t g_aq[(size_t)M_TOT * KKC];

// ---------------- K1: weight per-column max (+ reset ascale) ----------------
__global__ void k_wscale(const float* __restrict__ w) {
    int j = blockIdx.x * blockDim.x + threadIdx.x;
    if (j >= KKC) return;
    g_ascale[j] = 0.f;
    float m = 0.f;
    for (int o = 0; o < C_OUTC; ++o)
        m = fmaxf(m, fabsf(w[o * KKC + j]));
    g_wscale[j] = m;
}

// ---------------- K2: activation per-(c,kh,kw) max -------------------------
__global__ void k_ascale(const float* __restrict__ x) {
    int c = blockIdx.x, b = blockIdx.y;
    float m[9];
#pragma unroll
    for (int v = 0; v < 9; ++v) m[v] = 0.f;

    const float* xb = x + (((size_t)b * C_INC + c) << 12);
    for (int p = threadIdx.x; p < L_IMG; p += 256) {
        int h = p >> 6, w = p & 63;
        float a = fabsf(xb[p]);
        bool h0 = (h < HDIM - 1);
        bool h2 = (h > 0);
        bool w0 = (w < WDIM - 1);
        bool w2 = (w > 0);
        if (h0 && w0) m[0] = fmaxf(m[0], a);
        if (h0)       m[1] = fmaxf(m[1], a);
        if (h0 && w2) m[2] = fmaxf(m[2], a);
        if (w0)       m[3] = fmaxf(m[3], a);
        m[4] = fmaxf(m[4], a);
        if (w2)       m[5] = fmaxf(m[5], a);
        if (h2 && w0) m[6] = fmaxf(m[6], a);
        if (h2)       m[7] = fmaxf(m[7], a);
        if (h2 && w2) m[8] = fmaxf(m[8], a);
    }

    __shared__ float sm[256];
    for (int v = 0; v < 9; ++v) {
        sm[threadIdx.x] = m[v];
        __syncthreads();
        for (int s = 128; s > 0; s >>= 1) {
            if (threadIdx.x < s)
                sm[threadIdx.x] = fmaxf(sm[threadIdx.x], sm[threadIdx.x + s]);
            __syncthreads();
        }
        if (threadIdx.x == 0)
            atomicMax((int*)&g_ascale[c * 9 + v], __float_as_int(sm[0]));
        __syncthreads();
    }
}

// ---------------- K3: smooth scales + per-tensor quant scales ---------------
__global__ void k_scale() {
    __shared__ float red[256];
    __shared__ float s_sx_sh;
    int tid = threadIdx.x;

    float mx = 0.f, mw = 0.f;
    for (int j = tid; j < KKC; j += 256) {
        float a = g_ascale[j];
        float w = g_wscale[j];
        float s = __fdiv_rn(__fsqrt_rn(a), __fsqrt_rn(w));
        if (s == 0.f) s = 1.f;
        g_scale[j] = s;
        mx = fmaxf(mx, __fdiv_rn(a, s));
        mw = fmaxf(mw, w * s);
    }

    red[tid] = mx; __syncthreads();
    for (int s = 128; s > 0; s >>= 1) {
        if (tid < s) red[tid] = fmaxf(red[tid], red[tid + s]);
        __syncthreads();
    }
    if (tid == 0) {
        float sx = __fdiv_rn(red[0], 127.f);
        if (sx == 0.f) sx = 1.f;
        g_sx = sx; s_sx_sh = sx;
    }
    __syncthreads();

    red[tid] = mw; __syncthreads();
    for (int s = 128; s > 0; s >>= 1) {
        if (tid < s) red[tid] = fmaxf(red[tid], red[tid + s]);
        __syncthreads();
    }
    if (tid == 0) {
        float sw = __fdiv_rn(red[0], 127.f);
        if (sw == 0.f) sw = 1.f;
        g_sw = sw;
    }
    __syncthreads();

    float sx = s_sx_sh;
    for (int j = tid; j < KKC; j += 256)
        g_qfx[j] = __fdiv_rn(1.f, g_scale[j] * sx);
}

// ---------------- K4: quantize weights --------------------------------------
__global__ void k_wq(const float* __restrict__ w) {
    int i = blockIdx.x * blockDim.x + threadIdx.x;
    if (i >= C_OUTC * KKC) return;
    int j = i % KKC;
    float t = w[i] * g_scale[j];
    float q = rintf(__fdiv_rn(t, g_sw));
    q = fminf(fmaxf(q, -127.f), 127.f);
    g_wq[i] = (int8_t)(int)q;
}

// ---------------- K5: fused im2col + quantization (smem-staged) -------------
__global__ void __launch_bounds__(256) k_aq(const float* __restrict__ x) {
    extern __shared__ char dsm[];
    float*  qfx_s = (float*)dsm;
    float*  xs    = qfx_s + KKC;
    int8_t* aqs   = (int8_t*)(xs + 8 * 3 * 66);

    int tid = threadIdx.x;
    int bh  = blockIdx.x;
    int b   = bh >> 6, h = bh & 63;
    int g   = tid >> 5, lane = tid & 31;

    for (int j = tid; j < KKC; j += 256) qfx_s[j] = g_qfx[j];

    float* xg = xs + g * (3 * 66);

    for (int c0 = 0; c0 < C_INC; c0 += 8) {
        int c = c0 + g;
        __syncthreads();
        const float* xb = x + (((size_t)b * C_INC + c) << 12);
#pragma unroll
        for (int r = 0; r < 3; ++r) {
            int hh = h + r - 1;
            float v0 = 0.f, v1 = 0.f;
            if ((unsigned)hh < (unsigned)HDIM) {
                v0 = xb[(hh << 6) + lane];
                v1 = xb[(hh << 6) + lane + 32];
            }
            xg[r * 66 + 1 + lane]  = v0;
            xg[r * 66 + 33 + lane] = v1;
            if (lane == 0) { xg[r * 66] = 0.f; xg[r * 66 + 65] = 0.f; }
        }
        __syncthreads();
#pragma unroll
        for (int half = 0; half < 2; ++half) {
            int w = lane + half * 32;
#pragma unroll
            for (int e = 0; e < 9; ++e) {
                const int kh = e / 3, kw = e % 3;
                float v = xg[kh * 66 + w + kw];
                float q = rintf(v * qfx_s[c * 9 + e]);
                q = fminf(fmaxf(q, -127.f), 127.f);
                aqs[w * SSTR + c * 9 + e] = (int8_t)(int)q;
            }
        }
    }
    __syncthreads();

    int* dst = (int*)g_aq;
    for (int idx = tid; idx < 64 * KWORDS; idx += 256) {
        int row = idx / KWORDS;
        int col = idx - row * KWORDS;
        dst[((size_t)(bh * 64 + row)) * KWORDS + col] =
            *(const int*)(aqs + row * SSTR + col * 4);
    }
}

// ---------------- K6: optimized dp4a GEMM -----------------------------------
// C[M,N] = Aq * Wq^T. 256 thr, 128x128 tile, 8x8 micro-tile (strided 16),
// LDS.128 fragment loads, 2-stage cp.async, smem-transposed epilogue.

__device__ __forceinline__ void cp16(void* smem_dst, const void* gmem_src) {
    unsigned s = (unsigned)__cvta_generic_to_shared(smem_dst);
    asm volatile("cp.async.cg.shared.global [%0], [%1], 16;\n"
                 :: "r"(s), "l"(gmem_src));
}

__global__ void __launch_bounds__(256, 1) k_gemm_dp(const float* __restrict__ bias,
                                                    float* __restrict__ out) {
    __shared__ __align__(16) unsigned char sm[4 * ASTAGE];   // 40 KB
    unsigned char* As = sm;
    unsigned char* Bs = sm + 2 * ASTAGE;

    int tid = threadIdx.x;
    int tr = tid & 15, tc = tid >> 4;
    int m0 = blockIdx.x * BM;
    int n0 = blockIdx.y * BN;

    int acc[8][8];
#pragma unroll
    for (int i = 0; i < 8; ++i)
#pragma unroll
        for (int j = 0; j < 8; ++j) acc[i][j] = 0;

    const int4* Ag = (const int4*)g_aq;   // 72 int4 per row
    const int4* Bg = (const int4*)g_wq;

    auto load_stage = [&](int kt, int s) {
#pragma unroll
        for (int it = 0; it < 2; ++it) {
            int f4  = tid + it * 256;      // 512 int4 per operand tile
            int row = f4 >> 2;
            int c4  = f4 & 3;
            cp16(As + s * ASTAGE + row * ASTRIDE + c4 * 16,
                 Ag + (size_t)(m0 + row) * 72 + kt * 4 + c4);
            cp16(Bs + s * ASTAGE + row * ASTRIDE + c4 * 16,
                 Bg + (size_t)(n0 + row) * 72 + kt * 4 + c4);
        }
        asm volatile("cp.async.commit_group;\n" ::: "memory");
    };

    load_stage(0, 0);

    for (int kt = 0; kt < KT_STEPS; ++kt) {
        if (kt + 1 < KT_STEPS) {
            load_stage(kt + 1, (kt + 1) & 1);
            asm volatile("cp.async.wait_group 1;\n" ::: "memory");
        } else {
            asm volatile("cp.async.wait_group 0;\n" ::: "memory");
        }
        __syncthreads();

        const unsigned char* Ab = As + (kt & 1) * ASTAGE;
        const unsigned char* Bb = Bs + (kt & 1) * ASTAGE;

#pragma unroll
        for (int s = 0; s < 4; ++s) {      // 4 sub-chunks of 16 B
            int4 av[8], bv[8];
#pragma unroll
            for (int i = 0; i < 8; ++i)
                av[i] = *(const int4*)(Ab + (tr + i * 16) * ASTRIDE + s * 16);
#pragma unroll
            for (int j = 0; j < 8; ++j)
                bv[j] = *(const int4*)(Bb + (tc + j * 16) * ASTRIDE + s * 16);
#pragma unroll
            for (int i = 0; i < 8; ++i)
#pragma unroll
                for (int j = 0; j < 8; ++j) {
                    int v = acc[i][j];
                    v = __dp4a(av[i].x, bv[j].x, v);
                    v = __dp4a(av[i].y, bv[j].y, v);
                    v = __dp4a(av[i].z, bv[j].z, v);
                    v = __dp4a(av[i].w, bv[j].w, v);
                    acc[i][j] = v;
                }
        }
        __syncthreads();
    }

    // ---- epilogue: per-j smem transpose -> coalesced NCHW stores -----------
    float osc = g_sx * g_sw;
    int b_img = m0 >> 12;
    int p0 = m0 & 4095;
    float* sbuf = (float*)sm;              // 16 x 132 floats = 8448 B

#pragma unroll
    for (int j = 0; j < 8; ++j) {
        __syncthreads();
#pragma unroll
        for (int i = 0; i < 8; ++i)
            sbuf[tc * 132 + tr + i * 16] = (float)acc[i][j];
        __syncthreads();

        int ch = tid >> 4;                 // 0..15
        int pp = (tid & 15) * 8;
        int o  = n0 + j * 16 + ch;
        float bz = bias[o];
        float* op = out + (((size_t)b_img * C_OUTC + o) << 12) + p0 + pp;
        const float* sp = sbuf + ch * 132 + pp;
        float4 r0, r1;
        r0.x = sp[0] * osc + bz;  r0.y = sp[1] * osc + bz;
        r0.z = sp[2] * osc + bz;  r0.w = sp[3] * osc + bz;
        r1.x = sp[4] * osc + bz;  r1.y = sp[5] * osc + bz;
        r1.z = sp[6] * osc + bz;  r1.w = sp[7] * osc + bz;
        *(float4*)op       = r0;
        *(float4*)(op + 4) = r1;
    }
}

// ---------------- launch -----------------------------------------------------
extern "C" void kernel_launch(void* const* d_in, const int* in_sizes, int n_in,
                              void* d_out, int out_size) {
    const float* x    = (const float*)d_in[0];
    const float* wt   = (const float*)d_in[1];
    const float* bias = (const float*)d_in[2];
    float* out = (float*)d_out;

    cudaFuncSetAttribute(k_aq, cudaFuncAttributeMaxDynamicSharedMemorySize,
                         AQ_SMEM);

    k_wscale<<<(KKC + 255) / 256, 256>>>(wt);
    k_ascale<<<dim3(C_INC, BSZ), 256>>>(x);
    k_scale<<<1, 256>>>();
    k_wq<<<(C_OUTC * KKC) / 256, 256>>>(wt);
    k_aq<<<BSZ * HDIM, 256, AQ_SMEM>>>(x);
    k_gemm_dp<<<dim3(M_TOT / BM, C_OUTC / BN), 256>>>(bias, out);
}

// round 7
// speedup vs baseline: 1.6136x; 1.6136x over previous
#include <cuda_runtime.h>
#include <cuda_fp16.h>
#include <cstdint>
#include <cstddef>

// ---------------- problem constants ----------------
#define C_INC   128
#define C_OUTC  256
#define HDIM    64
#define WDIM    64
#define BSZ     16
#define KKC     1152          // C_IN * 9
#define M_TOT   65536
#define L_IMG   4096

// ---------------- k_aq staging (channel-half blocks) ----------------
#define STRH    1156          // strip row stride bytes (578 halves)
#define AQ_SMEM (576*4 + 8*3*66*4 + 64*STRH)   // 2304+6336+73984 = 82624

// ---------------- GEMM tiling ----------------
#define BM   128
#define BN   128
#define CHUNK_H 64            // k-halves per chunk (128 B)
#define KT_STEPS (KKC / CHUNK_H)   // 18
#define SROW 144              // smem stage row stride bytes (128 + 16 pad)
#define STG  (BM * SROW)      // 18432 per operand stage
#define GEMM_SMEM (4 * STG)   // 73728 (epilogue reuses: 128*129*4 = 66048)

// ---------------- device scratch ----------------
__device__ float g_wscale[KKC];
__device__ float g_ascale[KKC];
__device__ float g_scale[KKC];
__device__ float g_qfx[KKC];
__device__ float g_sx;
__device__ float g_sw;
__device__ __align__(16) __half g_wq_h[C_OUTC * KKC];
__device__ __align__(16) __half g_aq_h[(size_t)M_TOT * KKC];   // 151 MB

// ---------------- K1: weight per-column max (+ reset ascale) ----------------
__global__ void k_wscale(const float* __restrict__ w) {
    int j = blockIdx.x * blockDim.x + threadIdx.x;
    if (j >= KKC) return;
    g_ascale[j] = 0.f;
    float m = 0.f;
    for (int o = 0; o < C_OUTC; ++o)
        m = fmaxf(m, fabsf(w[o * KKC + j]));
    g_wscale[j] = m;
}

// ---------------- K2: activation per-(c,kh,kw) max -------------------------
__global__ void k_ascale(const float* __restrict__ x) {
    int c = blockIdx.x, b = blockIdx.y;
    float m[9];
#pragma unroll
    for (int v = 0; v < 9; ++v) m[v] = 0.f;

    const float* xb = x + (((size_t)b * C_INC + c) << 12);
    for (int p = threadIdx.x; p < L_IMG; p += 256) {
        int h = p >> 6, w = p & 63;
        float a = fabsf(xb[p]);
        bool h0 = (h < HDIM - 1);
        bool h2 = (h > 0);
        bool w0 = (w < WDIM - 1);
        bool w2 = (w > 0);
        if (h0 && w0) m[0] = fmaxf(m[0], a);
        if (h0)       m[1] = fmaxf(m[1], a);
        if (h0 && w2) m[2] = fmaxf(m[2], a);
        if (w0)       m[3] = fmaxf(m[3], a);
        m[4] = fmaxf(m[4], a);
        if (w2)       m[5] = fmaxf(m[5], a);
        if (h2 && w0) m[6] = fmaxf(m[6], a);
        if (h2)       m[7] = fmaxf(m[7], a);
        if (h2 && w2) m[8] = fmaxf(m[8], a);
    }

    __shared__ float sm[256];
    for (int v = 0; v < 9; ++v) {
        sm[threadIdx.x] = m[v];
        __syncthreads();
        for (int s = 128; s > 0; s >>= 1) {
            if (threadIdx.x < s)
                sm[threadIdx.x] = fmaxf(sm[threadIdx.x], sm[threadIdx.x + s]);
            __syncthreads();
        }
        if (threadIdx.x == 0)
            atomicMax((int*)&g_ascale[c * 9 + v], __float_as_int(sm[0]));
        __syncthreads();
    }
}

// ---------------- K3: smooth scales + per-tensor quant scales ---------------
__global__ void k_scale() {
    __shared__ float red[256];
    __shared__ float s_sx_sh;
    int tid = threadIdx.x;

    float mx = 0.f, mw = 0.f;
    for (int j = tid; j < KKC; j += 256) {
        float a = g_ascale[j];
        float w = g_wscale[j];
        float s = __fdiv_rn(__fsqrt_rn(a), __fsqrt_rn(w));
        if (s == 0.f) s = 1.f;
        g_scale[j] = s;
        mx = fmaxf(mx, __fdiv_rn(a, s));
        mw = fmaxf(mw, w * s);
    }

    red[tid] = mx; __syncthreads();
    for (int s = 128; s > 0; s >>= 1) {
        if (tid < s) red[tid] = fmaxf(red[tid], red[tid + s]);
        __syncthreads();
    }
    if (tid == 0) {
        float sx = __fdiv_rn(red[0], 127.f);
        if (sx == 0.f) sx = 1.f;
        g_sx = sx; s_sx_sh = sx;
    }
    __syncthreads();

    red[tid] = mw; __syncthreads();
    for (int s = 128; s > 0; s >>= 1) {
        if (tid < s) red[tid] = fmaxf(red[tid], red[tid + s]);
        __syncthreads();
    }
    if (tid == 0) {
        float sw = __fdiv_rn(red[0], 127.f);
        if (sw == 0.f) sw = 1.f;
        g_sw = sw;
    }
    __syncthreads();

    float sx = s_sx_sh;
    for (int j = tid; j < KKC; j += 256)
        g_qfx[j] = __fdiv_rn(1.f, g_scale[j] * sx);
}

// ---------------- K4: quantize weights -> fp16 ------------------------------
__global__ void k_wq(const float* __restrict__ w) {
    int i = blockIdx.x * blockDim.x + threadIdx.x;
    if (i >= C_OUTC * KKC) return;
    int j = i % KKC;
    float t = w[i] * g_scale[j];
    float q = rintf(__fdiv_rn(t, g_sw));
    q = fminf(fmaxf(q, -127.f), 127.f);
    g_wq_h[i] = __float2half_rn(q);        // small integer: exact in fp16
}

// ---------------- K5: fused im2col + quantization -> fp16 -------------------
// grid (1024 strips, 2 channel-halves). Each block: 64 channels x 64 positions.
__global__ void __launch_bounds__(256) k_aq(const float* __restrict__ x) {
    extern __shared__ char dsm[];
    float*  qfx_s = (float*)dsm;                   // 576
    float*  xs    = qfx_s + 576;                   // 8 * 3 * 66
    __half* aqs   = (__half*)(xs + 8 * 3 * 66);    // 64 * STRH bytes

    int tid = threadIdx.x;
    int bh  = blockIdx.x;          // b*64 + h
    int ch2 = blockIdx.y;          // channel half
    int b   = bh >> 6, h = bh & 63;
    int g   = tid >> 5, lane = tid & 31;

    for (int j = tid; j < 576; j += 256) qfx_s[j] = g_qfx[ch2 * 576 + j];

    float* xg = xs + g * (3 * 66);

    for (int c0 = 0; c0 < 64; c0 += 8) {
        int cl = c0 + g;                       // local channel 0..63
        int c  = ch2 * 64 + cl;                // global channel
        __syncthreads();
        const float* xb = x + (((size_t)b * C_INC + c) << 12);
#pragma unroll
        for (int r = 0; r < 3; ++r) {
            int hh = h + r - 1;
            float v0 = 0.f, v1 = 0.f;
            if ((unsigned)hh < (unsigned)HDIM) {
                v0 = xb[(hh << 6) + lane];
                v1 = xb[(hh << 6) + lane + 32];
            }
            xg[r * 66 + 1 + lane]  = v0;
            xg[r * 66 + 33 + lane] = v1;
            if (lane == 0) { xg[r * 66] = 0.f; xg[r * 66 + 65] = 0.f; }
        }
        __syncthreads();
#pragma unroll
        for (int half = 0; half < 2; ++half) {
            int w = lane + half * 32;
            __half* ar = (__half*)((char*)aqs + w * STRH);
#pragma unroll
            for (int e = 0; e < 9; ++e) {
                const int kh = e / 3, kw = e % 3;
                float v = xg[kh * 66 + w + kw];
                float q = rintf(v * qfx_s[cl * 9 + e]);
                q = fminf(fmaxf(q, -127.f), 127.f);
                ar[cl * 9 + e] = __float2half_rn(q);
            }
        }
    }
    __syncthreads();

    // writeout: 64 rows x 288 ints (576 halves), coalesced
    int* dst = (int*)g_aq_h;
    for (int idx = tid; idx < 64 * 288; idx += 256) {
        int row = idx / 288;
        int col = idx - row * 288;
        dst[((size_t)(bh * 64 + row)) * 576 + ch2 * 288 + col] =
            *(const int*)((char*)aqs + row * STRH + col * 4);
    }
}

// ---------------- K6: fp16 tensor-core GEMM (fallback HMMA path) ------------
__device__ __forceinline__ void cp16(void* smem_dst, const void* gmem_src) {
    unsigned s = (unsigned)__cvta_generic_to_shared(smem_dst);
    asm volatile("cp.async.cg.shared.global [%0], [%1], 16;\n"
                 :: "r"(s), "l"(gmem_src));
}

__device__ __forceinline__ void ldsm4(uint32_t* r, const void* p) {
    unsigned a = (unsigned)__cvta_generic_to_shared(p);
    asm volatile("ldmatrix.sync.aligned.m8n8.x4.shared.b16 {%0,%1,%2,%3}, [%4];"
                 : "=r"(r[0]), "=r"(r[1]), "=r"(r[2]), "=r"(r[3]) : "r"(a));
}

__device__ __forceinline__ void mma_f16(float* c, const uint32_t* a,
                                        uint32_t b0, uint32_t b1) {
    asm volatile(
        "mma.sync.aligned.m16n8k16.row.col.f32.f16.f16.f32 "
        "{%0,%1,%2,%3}, {%4,%5,%6,%7}, {%8,%9}, {%0,%1,%2,%3};\n"
        : "+f"(c[0]), "+f"(c[1]), "+f"(c[2]), "+f"(c[3])
        : "r"(a[0]), "r"(a[1]), "r"(a[2]), "r"(a[3]), "r"(b0), "r"(b1));
}

__global__ void __launch_bounds__(256, 2) k_gemm_h(const float* __restrict__ bias,
                                                   float* __restrict__ out) {
    extern __shared__ __align__(16) char smem[];
    char* A0 = smem;                 // stages: A0 A1 B0 B1
    char* B0 = smem + 2 * STG;

    int tid = threadIdx.x;
    int warpId = tid >> 5, lane = tid & 31;
    int wm = warpId & 1, wn = warpId >> 1;   // 2 x 4 warps
    int m0 = blockIdx.x * BM;
    int n0 = blockIdx.y * BN;

    float acc[4][4][4];
#pragma unroll
    for (int i = 0; i < 4; ++i)
#pragma unroll
        for (int j = 0; j < 4; ++j)
#pragma unroll
            for (int r = 0; r < 4; ++r) acc[i][j][r] = 0.f;

    const char* Ag = (const char*)g_aq_h;    // row stride 2304 B
    const char* Bg = (const char*)g_wq_h;

    auto load_stage = [&](int kt, int s) {
#pragma unroll
        for (int it = 0; it < 4; ++it) {
            int f = tid + it * 256;          // 1024 granules per operand
            int row = f >> 3, c16 = f & 7;
            cp16(A0 + s * STG + row * SROW + c16 * 16,
                 Ag + (size_t)(m0 + row) * 2304 + kt * 128 + c16 * 16);
            cp16(B0 + s * STG + row * SROW + c16 * 16,
                 Bg + (size_t)(n0 + row) * 2304 + kt * 128 + c16 * 16);
        }
        asm volatile("cp.async.commit_group;\n" ::: "memory");
    };

    load_stage(0, 0);

    // ldmatrix lane addressing (computed once)
    int lrow = lane & 15;
    int lcol = (lane >> 4) * 16;

    for (int kt = 0; kt < KT_STEPS; ++kt) {
        if (kt + 1 < KT_STEPS) {
            load_stage(kt + 1, (kt + 1) & 1);
            asm volatile("cp.async.wait_group 1;\n" ::: "memory");
        } else {
            asm volatile("cp.async.wait_group 0;\n" ::: "memory");
        }
        __syncthreads();

        const char* Ab = A0 + (kt & 1) * STG;
        const char* Bb = B0 + (kt & 1) * STG;

#pragma unroll
        for (int ks = 0; ks < 4; ++ks) {     // 4 x k16 per 64-half chunk
            uint32_t af[4][4], bf[2][4];
#pragma unroll
            for (int i = 0; i < 4; ++i)
                ldsm4(af[i], Ab + (wm * 64 + i * 16 + lrow) * SROW + ks * 32 + lcol);
#pragma unroll
            for (int j2 = 0; j2 < 2; ++j2)
                ldsm4(bf[j2], Bb + (wn * 32 + j2 * 16 + lrow) * SROW + ks * 32 + lcol);
#pragma unroll
            for (int i = 0; i < 4; ++i)
#pragma unroll
                for (int j = 0; j < 4; ++j) {
                    int j2 = j >> 1, hi = j & 1;
                    mma_f16(acc[i][j], af[i],
                            hi ? bf[j2][1] : bf[j2][0],
                            hi ? bf[j2][3] : bf[j2][2]);
                }
        }
        __syncthreads();
    }

    // ---- epilogue: smem transpose (stride 129) -> coalesced NCHW stores ----
    float* sbuf = (float*)smem;              // 128 x 129 floats = 66048 B
    int grp = lane >> 2, tig = lane & 3;
    __syncthreads();
#pragma unroll
    for (int i = 0; i < 4; ++i)
#pragma unroll
        for (int j = 0; j < 4; ++j)
#pragma unroll
            for (int r = 0; r < 4; ++r) {
                int m = wm * 64 + i * 16 + grp + (r >> 1) * 8;
                int n = wn * 32 + j * 8 + tig * 2 + (r & 1);
                sbuf[m * 129 + n] = acc[i][j][r];
            }
    __syncthreads();

    float osc = g_sx * g_sw;
    int b_img = m0 >> 12;
    int p0 = m0 & 4095;
    int m = tid & 127, nh = tid >> 7;        // 128 m-lanes x 2 n-halves
#pragma unroll
    for (int nn = 0; nn < 64; ++nn) {
        int n = nh * 64 + nn;
        int o = n0 + n;
        float v = sbuf[m * 129 + n] * osc + __ldg(&bias[o]);
        out[(((size_t)b_img * C_OUTC + o) << 12) + p0 + m] = v;
    }
}

// ---------------- launch -----------------------------------------------------
extern "C" void kernel_launch(void* const* d_in, const int* in_sizes, int n_in,
                              void* d_out, int out_size) {
    const float* x    = (const float*)d_in[0];
    const float* wt   = (const float*)d_in[1];
    const float* bias = (const float*)d_in[2];
    float* out = (float*)d_out;

    cudaFuncSetAttribute(k_aq, cudaFuncAttributeMaxDynamicSharedMemorySize,
                         AQ_SMEM);
    cudaFuncSetAttribute(k_gemm_h, cudaFuncAttributeMaxDynamicSharedMemorySize,
                         GEMM_SMEM);

    k_wscale<<<(KKC + 255) / 256, 256>>>(wt);
    k_ascale<<<dim3(C_INC, BSZ), 256>>>(x);
    k_scale<<<1, 256>>>();
    k_wq<<<(C_OUTC * KKC) / 256, 256>>>(wt);
    k_aq<<<dim3(BSZ * HDIM, 2), 256, AQ_SMEM>>>(x);
    k_gemm_h<<<dim3(M_TOT / BM, C_OUTC / BN), 256, GEMM_SMEM>>>(bias, out);
}